// round 15
// baseline (speedup 1.0000x reference)
#include <cuda_runtime.h>
#include <cuda_bf16.h>
#include <cstdint>

// ConvPooler — per-token dot(h[b,s,:], w) + bias scattered into
// out[b, gene_pos[b,s]] over a [B, 60000] zeroed buffer; pad id 60000 dropped.
// B=32, S=2048, D=512, FULL_SEQ_LEN=60000. gene_pos is int32.
//
// Graph with PARALLEL branches (capture-fork on a side stream):
//   branch A (main): conv -> dense __device__ scratch (pure read stream)
//   branch B (side): zero-fill out[]           — concurrent with A
//   join:            scatter g_vals -> out      — after both
// Critical path = conv (at HBM read plateau) + tiny scatter.

#define B_DIM 32
#define S_DIM 2048
#define D_DIM 512
#define FULL_SEQ 60000
#define NTOK (B_DIM * S_DIM)          // 65536 tokens

// Dense per-token conv results (bias added). 256 KB static scratch.
__device__ float g_vals[NTOK];

// ---------------------------------------------------------------------------
// Zero kernel (branch B): exact-fit grid, one float4 per thread.
// ---------------------------------------------------------------------------
__global__ void zero_out_kernel(float4* __restrict__ out, int n4) {
    int i = blockIdx.x * blockDim.x + threadIdx.x;
    if (i < n4) out[i] = make_float4(0.f, 0.f, 0.f, 0.f);
}

// ---------------------------------------------------------------------------
// Conv kernel (branch A): one warp per token — R2's proven 24.8us shape,
// but writing DENSE results to g_vals (L2-resident) instead of scattering.
// ---------------------------------------------------------------------------
__global__ __launch_bounds__(256, 8)
void conv_dense_kernel(const float4* __restrict__ h,   // [B*S, D/4]
                       const float4* __restrict__ w,   // [D/4]
                       const float* __restrict__ bias) // [1]
{
    const int warp_id = (blockIdx.x * blockDim.x + threadIdx.x) >> 5;
    const int lane    = threadIdx.x & 31;
    if (warp_id >= NTOK) return;

    const float4* hrow = h + (size_t)warp_id * (D_DIM / 4);

    float acc = 0.f;
#pragma unroll
    for (int j = 0; j < 4; ++j) {
        const int idx = lane + 32 * j;
        float4 hv = hrow[idx];
        float4 wv = __ldg(&w[idx]);   // broadcast; L1-resident after first touch
        acc = fmaf(hv.x, wv.x, acc);
        acc = fmaf(hv.y, wv.y, acc);
        acc = fmaf(hv.z, wv.z, acc);
        acc = fmaf(hv.w, wv.w, acc);
    }

#pragma unroll
    for (int off = 16; off > 0; off >>= 1)
        acc += __shfl_xor_sync(0xFFFFFFFFu, acc, off);

    if (lane == 0)
        g_vals[warp_id] = acc + bias[0];
}

// ---------------------------------------------------------------------------
// Scatter kernel (join): one thread per token. All inputs L2-resident.
// ---------------------------------------------------------------------------
__global__ void scatter_kernel(const int* __restrict__ gene_pos,  // [B*S]
                               float* __restrict__ out) {         // [B, FULL_SEQ]
    const int tok = blockIdx.x * blockDim.x + threadIdx.x;
    if (tok >= NTOK) return;
    const int gp = gene_pos[tok];
    if (gp >= 0 && gp < FULL_SEQ) {
        const int row = tok >> 11;          // tok / S_DIM
        out[(size_t)row * FULL_SEQ + (size_t)gp] = g_vals[tok];
    }
}

// ---------------------------------------------------------------------------
// Launch — capture-fork the zero-fill onto a side stream so it runs
// concurrently with the conv; join before the scatter.
// Inputs mapped by element count: h=33554432, gene_pos=65536, w=512, b=1.
// ---------------------------------------------------------------------------
extern "C" void kernel_launch(void* const* d_in, const int* in_sizes, int n_in,
                              void* d_out, int out_size) {
    const void* h_p = nullptr;
    const void* gp_p = nullptr;
    const void* w_p = nullptr;
    const void* b_p = nullptr;
    for (int i = 0; i < n_in; ++i) {
        switch (in_sizes[i]) {
            case B_DIM * S_DIM * D_DIM: h_p  = d_in[i]; break;  // 33,554,432
            case B_DIM * S_DIM:         gp_p = d_in[i]; break;  // 65,536
            case D_DIM:                 w_p  = d_in[i]; break;  // 512
            case 1:                     b_p  = d_in[i]; break;
            default: break;
        }
    }

    const float4* h  = (const float4*)h_p;
    const int*    gp = (const int*)gp_p;
    const float4* w  = (const float4*)w_p;
    const float*  b  = (const float*)b_p;
    float* out = (float*)d_out;

    const int n4 = out_size / 4;            // 480,000 float4
    const int zb = (n4 + 255) / 256;        // 1875 blocks

    // Lazily created host-side objects (no device memory involved).
    static cudaStream_t s_side = nullptr;
    static cudaEvent_t  s_fork = nullptr, s_join = nullptr;
    static bool s_tried = false;
    if (!s_tried) {
        s_tried = true;
        if (cudaStreamCreateWithFlags(&s_side, cudaStreamNonBlocking) != cudaSuccess)
            s_side = nullptr;
        if (s_side) {
            if (cudaEventCreateWithFlags(&s_fork, cudaEventDisableTiming) != cudaSuccess ||
                cudaEventCreateWithFlags(&s_join, cudaEventDisableTiming) != cudaSuccess) {
                s_side = nullptr;  // fall back to sequential
            }
        }
    }

    if (s_side) {
        // Fork: side stream joins the (possibly capturing) main stream.
        cudaEventRecord(s_fork, 0);
        cudaStreamWaitEvent(s_side, s_fork, 0);

        // Branch B: zero-fill, concurrent with conv.
        zero_out_kernel<<<zb, 256, 0, s_side>>>((float4*)out, n4);
        cudaEventRecord(s_join, s_side);

        // Branch A: conv -> dense scratch (one warp/token, 8192 blocks).
        conv_dense_kernel<<<(NTOK * 32) / 256, 256>>>(h, w, b);

        // Join, then scatter.
        cudaStreamWaitEvent(0, s_join, 0);
        scatter_kernel<<<NTOK / 256, 256>>>(gp, out);
    } else {
        // Sequential fallback (still correct).
        zero_out_kernel<<<zb, 256>>>((float4*)out, n4);
        conv_dense_kernel<<<(NTOK * 32) / 256, 256>>>(h, w, b);
        scatter_kernel<<<NTOK / 256, 256>>>(gp, out);
    }
}

// round 16
// speedup vs baseline: 1.0956x; 1.0956x over previous
#include <cuda_runtime.h>
#include <cuda_bf16.h>
#include <cstdint>

// ConvPooler — per-token dot(h[b,s,:], w) + bias scattered into
// out[b, gene_pos[b,s]] over a [B, 60000] zeroed buffer; pad id 60000 dropped.
// B=32, S=2048, D=512, FULL_SEQ_LEN=60000. gene_pos is int32.
//
// Two graph nodes:
//   1. cudaMemsetAsync(out, 0)  — native memset node (driver fill path; the
//      R15 profile showed a zero-fill KERNEL wastes ~3us on launch ramp +
//      one-store-per-thread latency, DRAM 0%).
//   2. conv+scatter kernel — R2-proven shape: one warp per token, float4
//      coalesced loads, warp shfl reduce, direct guarded scatter (24.83us,
//      HBM read plateau ~5.6 TB/s).

#define B_DIM 32
#define S_DIM 2048
#define D_DIM 512
#define FULL_SEQ 60000
#define NTOK (B_DIM * S_DIM)   // 65536 tokens

// ---------------------------------------------------------------------------
// Conv + scatter: one warp per token (exact R2 configuration, 24.83us).
// ---------------------------------------------------------------------------
__global__ __launch_bounds__(256, 8)
void conv_scatter_kernel(const float4* __restrict__ h,      // [B*S, D/4]
                         const int* __restrict__ gene_pos,  // [B*S] int32
                         const float4* __restrict__ w,      // [D/4]
                         const float* __restrict__ bias,    // [1]
                         float* __restrict__ out) {         // [B, FULL_SEQ]
    const int warp_id = (blockIdx.x * blockDim.x + threadIdx.x) >> 5;
    const int lane    = threadIdx.x & 31;
    if (warp_id >= NTOK) return;

    // Token row: 512 floats = 128 float4; lane + 32*j -> coalesced 128B/iter.
    const float4* hrow = h + (size_t)warp_id * (D_DIM / 4);

    float acc = 0.f;
#pragma unroll
    for (int j = 0; j < 4; ++j) {
        const int idx = lane + 32 * j;
        float4 hv = hrow[idx];
        float4 wv = __ldg(&w[idx]);   // broadcast; L1-resident after first touch
        acc = fmaf(hv.x, wv.x, acc);
        acc = fmaf(hv.y, wv.y, acc);
        acc = fmaf(hv.z, wv.z, acc);
        acc = fmaf(hv.w, wv.w, acc);
    }

    // Butterfly reduction across the warp.
#pragma unroll
    for (int off = 16; off > 0; off >>= 1)
        acc += __shfl_xor_sync(0xFFFFFFFFu, acc, off);

    if (lane == 0) {
        const int gp = gene_pos[warp_id];
        if (gp >= 0 && gp < FULL_SEQ) {      // pad id == FULL_SEQ dropped
            const int row = warp_id >> 11;   // warp_id / S_DIM
            out[(size_t)row * FULL_SEQ + (size_t)gp] = acc + bias[0];
        }
    }
}

// ---------------------------------------------------------------------------
// Launch — map inputs by element count (robust to metadata ordering):
// h=33554432, gene_pos=65536, w=512, b=1.
// ---------------------------------------------------------------------------
extern "C" void kernel_launch(void* const* d_in, const int* in_sizes, int n_in,
                              void* d_out, int out_size) {
    const void* h_p = nullptr;
    const void* gp_p = nullptr;
    const void* w_p = nullptr;
    const void* b_p = nullptr;
    for (int i = 0; i < n_in; ++i) {
        switch (in_sizes[i]) {
            case B_DIM * S_DIM * D_DIM: h_p  = d_in[i]; break;  // 33,554,432
            case B_DIM * S_DIM:         gp_p = d_in[i]; break;  // 65,536
            case D_DIM:                 w_p  = d_in[i]; break;  // 512
            case 1:                     b_p  = d_in[i]; break;
            default: break;
        }
    }

    // Node 1: zero the output via a native memset node (async, capturable).
    cudaMemsetAsync(d_out, 0, (size_t)out_size * sizeof(float), 0);

    // Node 2: conv + scatter (one warp/token: 65536 warps -> 8192 blocks).
    conv_scatter_kernel<<<(NTOK * 32) / 256, 256>>>(
        (const float4*)h_p, (const int*)gp_p, (const float4*)w_p,
        (const float*)b_p, (float*)d_out);
}